// round 15
// baseline (speedup 1.0000x reference)
#include <cuda_runtime.h>
#include <cuda_bf16.h>
#include <math.h>
#include <stdint.h>

// Problem dims (fixed by setup_inputs)
#define Bn 2
#define Sn 2048
#define Hn 1024
#define NHn 16
#define BHn 32        // Bn*NHn
#define NT 8          // series terms n=0..7
#define KT 128        // NHn*NT — GEMM N/K
#define KSn 8         // k-split chunks for k_Tg (8 x 256)

// PDL: plain sm_90+ PTX (no 'a' suffix). wait = block until stream-predecessor
// kernel fully completes (all its writes visible); launch_dependents = allow
// the next kernel's CTAs to begin scheduling. No-ops without the launch attr.
#define GDC_WAIT()   asm volatile("griddepcontrol.wait;" ::: "memory")
#define GDC_LAUNCH() asm volatile("griddepcontrol.launch_dependents;")

// ---------------- scratch (device globals; no allocations allowed) ----------
__device__ float g_wbar[32 * Hn];
__device__ float g_bbar[32];
__device__ float g_qm[BHn * Sn];                        // [bh][s]
__device__ __align__(16) __nv_bfloat16 g_Pt[Bn * KT * Sn];   // [b][col][k] bf16
__device__ __align__(16) __nv_bfloat16 g_hsT[(size_t)Bn * Hn * Sn]; // [b][j][k] bf16
__device__ float g_Tp[KSn * Bn * Hn * KT];              // partial T fp32
__device__ float g_T[Bn * Hn * KT];                     // [b][j][col]
__device__ float g_z[Bn * KT];                          // [b][h*8+n]
__device__ __align__(16) __nv_bfloat16 g_Ut[Bn * Hn * KT];   // [b][e][col] bf16

__constant__ float c_invf[NT] = {1.f, 1.f, 0.5f, 1.f/6.f, 1.f/24.f, 1.f/120.f,
                                 1.f/720.f, 1.f/5040.f};

// ---------------- warp-level bf16 MMA (sm_80+ baseline; ok on sm_103) -------
__device__ __forceinline__ void mma16816(float* d, const uint32_t* a, const uint32_t* b) {
    asm volatile(
        "mma.sync.aligned.m16n8k16.row.col.f32.bf16.bf16.f32 "
        "{%0,%1,%2,%3}, {%4,%5,%6,%7}, {%8,%9}, {%0,%1,%2,%3};"
        : "+f"(d[0]), "+f"(d[1]), "+f"(d[2]), "+f"(d[3])
        : "r"(a[0]), "r"(a[1]), "r"(a[2]), "r"(a[3]), "r"(b[0]), "r"(b[1]));
}
__device__ __forceinline__ uint32_t bf2u(float a, float b) {
    __nv_bfloat162 h2;
    h2.x = __float2bfloat16_rn(a);
    h2.y = __float2bfloat16_rn(b);
    return *(uint32_t*)&h2;
}

// ---------------- K1: fold Wq/Wk rows into per-head means ----------------
__global__ void k_bar(const float* __restrict__ Wq, const float* __restrict__ Wk,
                      const float* __restrict__ bq, const float* __restrict__ bk) {
    GDC_LAUNCH();          // first kernel; let qkm CTAs get resident early
    int idx = blockIdx.x * blockDim.x + threadIdx.x;
    if (idx < 32 * Hn) {
        int o = idx >> 10, k = idx & (Hn - 1);
        const float* W = (o < 16) ? Wq : Wk;
        int h = o & 15;
        float s = 0.f;
        #pragma unroll 4
        for (int d = 0; d < 64; d++) s += W[(h * 64 + d) * Hn + k];
        g_wbar[o * Hn + k] = s * (1.f / 64.f);
    }
    if (idx < 32) {
        const float* bb = (idx < 16) ? bq : bk;
        int h = idx & 15;
        float s = 0.f;
        for (int d = 0; d < 64; d++) s += bb[h * 64 + d];
        g_bbar[idx] = s * (1.f / 64.f);
    }
}

// ---------------- K2: qm/km via mma.sync, chunked K (32 rows/block) ---------
#define QPW 1032
#define QPA 136
__global__ void __launch_bounds__(256) k_qkm(const float* __restrict__ hs,
                                             const float* __restrict__ mask) {
    GDC_WAIT();            // needs g_wbar/g_bbar from k_bar
    extern __shared__ __align__(16) char qsm[];
    __nv_bfloat16* sW = (__nv_bfloat16*)qsm;                 // 66048 B
    __nv_bfloat16* sA = (__nv_bfloat16*)(qsm + 66048);       // 8704 B

    int t = threadIdx.x;
    int rb = blockIdx.x * 32;

    {
        int row = t >> 3, cb = (t & 7) * 128;
        const float* wrow = g_wbar + (size_t)row * Hn + cb;
        #pragma unroll
        for (int q = 0; q < 32; q += 2) {
            float4 v0 = *(const float4*)(wrow + q * 4);
            float4 v1 = *(const float4*)(wrow + q * 4 + 4);
            *(uint4*)&sW[row * QPW + cb + q * 4] =
                make_uint4(bf2u(v0.x, v0.y), bf2u(v0.z, v0.w),
                           bf2u(v1.x, v1.y), bf2u(v1.z, v1.w));
        }
    }

    int wid = t >> 5, lane = t & 31, g = lane >> 2, tg = lane & 3;
    int wm = wid & 1, wn = wid >> 1;
    int r0 = wm * 16 + g;
    float acc[4] = {};

    int arow = t >> 3, acb = (t & 7) * 16;
    const float* hrow = hs + (size_t)(rb + arow) * Hn + acb;

    for (int c = 0; c < 8; c++) {
        __syncthreads();
        {
            float4 v0 = *(const float4*)(hrow + c * 128 + 0);
            float4 v1 = *(const float4*)(hrow + c * 128 + 4);
            float4 v2 = *(const float4*)(hrow + c * 128 + 8);
            float4 v3 = *(const float4*)(hrow + c * 128 + 12);
            *(uint4*)&sA[arow * QPA + acb + 0] =
                make_uint4(bf2u(v0.x, v0.y), bf2u(v0.z, v0.w),
                           bf2u(v1.x, v1.y), bf2u(v1.z, v1.w));
            *(uint4*)&sA[arow * QPA + acb + 8] =
                make_uint4(bf2u(v2.x, v2.y), bf2u(v2.z, v2.w),
                           bf2u(v3.x, v3.y), bf2u(v3.z, v3.w));
        }
        __syncthreads();
        #pragma unroll
        for (int ks = 0; ks < 8; ks++) {
            int k0 = ks * 16;
            int kg = c * 128 + k0;
            uint32_t a[4];
            a[0] = *(const uint32_t*)(sA + r0 * QPA + k0 + 2 * tg);
            a[1] = *(const uint32_t*)(sA + (r0 + 8) * QPA + k0 + 2 * tg);
            a[2] = *(const uint32_t*)(sA + r0 * QPA + k0 + 8 + 2 * tg);
            a[3] = *(const uint32_t*)(sA + (r0 + 8) * QPA + k0 + 8 + 2 * tg);
            int n = wn * 8 + g;
            uint32_t bb[2];
            bb[0] = *(const uint32_t*)(sW + n * QPW + kg + 2 * tg);
            bb[1] = *(const uint32_t*)(sW + n * QPW + kg + 8 + 2 * tg);
            mma16816(acc, a, bb);
        }
    }
    GDC_LAUNCH();          // main compute done; epilogue stores remain

    int o0 = wn * 8 + 2 * tg;
    #pragma unroll
    for (int rr = 0; rr < 2; rr++) {
        int rg = rb + r0 + rr * 8;
        int b = rg >> 11, s = rg & (Sn - 1);
        float v0 = acc[rr * 2 + 0] + g_bbar[o0];
        float v1 = acc[rr * 2 + 1] + g_bbar[o0 + 1];
        if (o0 < 16) {
            g_qm[(b * NHn + o0) * Sn + s] = v0;
            g_qm[(b * NHn + o0 + 1) * Sn + s] = v1;
        } else {
            float mk = (mask[b * Sn + s] > 0.f) ? 1.f : 0.f;
            int h0 = o0 - 16;
            __nv_bfloat16* d0 = g_Pt + (size_t)(b * KT + h0 * 8) * Sn + s;
            __nv_bfloat16* d1 = g_Pt + (size_t)(b * KT + (h0 + 1) * 8) * Sn + s;
            float p0 = mk, p1 = mk;
            #pragma unroll
            for (int n = 0; n < NT; n++) {
                d0[(size_t)n * Sn] = __float2bfloat16_rn(p0);
                d1[(size_t)n * Sn] = __float2bfloat16_rn(p1);
                p0 *= v0; p1 *= v1;
            }
        }
    }
}

// ---------------- K3: transpose hs -> g_hsT bf16 [b][j][k] ----------------
__global__ void __launch_bounds__(256) k_tr(const float* __restrict__ hs) {
    GDC_WAIT();            // chain safety (transitive ordering)
    __shared__ float sm[64][33];
    int t = threadIdx.x;
    int k0 = blockIdx.x * 64, j0 = blockIdx.y * 32, b = blockIdx.z;
    #pragma unroll
    for (int i = 0; i < 2; i++) {
        int idx = t + 256 * i;
        int k = idx >> 3, jq = (idx & 7) * 4;
        float4 v = *(const float4*)&hs[(size_t)(b * Sn + k0 + k) * Hn + j0 + jq];
        sm[k][jq + 0] = v.x; sm[k][jq + 1] = v.y; sm[k][jq + 2] = v.z; sm[k][jq + 3] = v.w;
    }
    __syncthreads();
    GDC_LAUNCH();
    int jj = t >> 3, c = t & 7;
    uint32_t w[4];
    #pragma unroll
    for (int q = 0; q < 4; q++)
        w[q] = bf2u(sm[c * 8 + q * 2 + 0][jj], sm[c * 8 + q * 2 + 1][jj]);
    *(uint4*)(g_hsT + ((size_t)(b * Hn + j0 + jj)) * Sn + k0 + c * 8) =
        make_uint4(w[0], w[1], w[2], w[3]);
}

// ---------------- K4: z[b][col] = sum_k Pt[b][col][k] (8 cols/block) --------
__global__ void __launch_bounds__(256) k_z() {
    GDC_WAIT();            // needs g_Pt (via chain)
    int t = threadIdx.x;
    int w = t >> 5, l = t & 31;
    int col = blockIdx.x * 8 + w, b = blockIdx.y;
    const __nv_bfloat16* src = g_Pt + (size_t)(b * KT + col) * Sn;
    float s = 0.f;
    #pragma unroll
    for (int i = 0; i < 8; i++) {
        uint4 v = *(const uint4*)(src + (l + 32 * i) * 8);
        uint32_t u[4] = {v.x, v.y, v.z, v.w};
        #pragma unroll
        for (int q = 0; q < 4; q++) {
            float2 f = __bfloat1622float2(*(__nv_bfloat162*)&u[q]);
            s += f.x + f.y;
        }
    }
    GDC_LAUNCH();
    #pragma unroll
    for (int off = 16; off; off >>= 1) s += __shfl_xor_sync(0xffffffffu, s, off);
    if (l == 0) g_z[b * KT + col] = s;
}

// ---------------- K5: T-GEMM via mma.sync: Tp = hsT @ Pt^T (128x128x256) ----
#define PAD 264
__global__ void __launch_bounds__(256) k_Tg() {
    GDC_WAIT();            // needs g_hsT + g_Pt (via chain)
    extern __shared__ __align__(16) __nv_bfloat16 smem[];
    __nv_bfloat16* sA = smem;               // [128][264]
    __nv_bfloat16* sB = smem + 128 * PAD;   // [128][264]
    int t = threadIdx.x;
    int jt = blockIdx.x, kc = blockIdx.y, b = blockIdx.z;
    int k0g = kc * 256;

    const __nv_bfloat16* Asrc = g_hsT + ((size_t)(b * Hn + jt * 128)) * Sn + k0g;
    const __nv_bfloat16* Bsrc = g_Pt + ((size_t)(b * KT)) * Sn + k0g;
    #pragma unroll
    for (int i = 0; i < 16; i++) {
        int idx = t + 256 * i;
        int m = idx >> 5, c = idx & 31;
        *(uint4*)(sA + m * PAD + c * 8) = *(const uint4*)(Asrc + (size_t)m * Sn + c * 8);
        *(uint4*)(sB + m * PAD + c * 8) = *(const uint4*)(Bsrc + (size_t)m * Sn + c * 8);
    }
    __syncthreads();

    int wid = t >> 5, lane = t & 31;
    int wm = wid >> 1, wn = wid & 1;
    int R = wm * 32, Cb = wn * 64;
    int g = lane >> 2, tg = lane & 3;

    float acc[2][8][4];
    #pragma unroll
    for (int mi = 0; mi < 2; mi++)
        #pragma unroll
        for (int ni = 0; ni < 8; ni++)
            #pragma unroll
            for (int q = 0; q < 4; q++) acc[mi][ni][q] = 0.f;

    #pragma unroll 4
    for (int ks = 0; ks < 16; ks++) {
        int k0 = ks * 16;
        uint32_t a[2][4];
        #pragma unroll
        for (int mi = 0; mi < 2; mi++) {
            int r0 = R + mi * 16 + g;
            a[mi][0] = *(const uint32_t*)(sA + r0 * PAD + k0 + 2 * tg);
            a[mi][1] = *(const uint32_t*)(sA + (r0 + 8) * PAD + k0 + 2 * tg);
            a[mi][2] = *(const uint32_t*)(sA + r0 * PAD + k0 + 8 + 2 * tg);
            a[mi][3] = *(const uint32_t*)(sA + (r0 + 8) * PAD + k0 + 8 + 2 * tg);
        }
        #pragma unroll
        for (int ni = 0; ni < 8; ni++) {
            int n = Cb + ni * 8 + g;
            uint32_t bb[2];
            bb[0] = *(const uint32_t*)(sB + n * PAD + k0 + 2 * tg);
            bb[1] = *(const uint32_t*)(sB + n * PAD + k0 + 8 + 2 * tg);
            mma16816(acc[0][ni], a[0], bb);
            mma16816(acc[1][ni], a[1], bb);
        }
    }
    GDC_LAUNCH();          // MMA done; stores remain

    #pragma unroll
    for (int mi = 0; mi < 2; mi++) {
        int j = jt * 128 + R + mi * 16 + g;
        float* base = g_Tp + ((size_t)((kc * Bn + b) * Hn + j)) * KT;
        #pragma unroll
        for (int ni = 0; ni < 8; ni++) {
            int col = Cb + ni * 8 + 2 * tg;
            *(float2*)(base + col) = make_float2(acc[mi][ni][0], acc[mi][ni][1]);
            *(float2*)(base + 8 * KT + col) = make_float2(acc[mi][ni][2], acc[mi][ni][3]);
        }
    }
}

// ---------------- K6: reduce T partials (deterministic, float4) -------------
__global__ void __launch_bounds__(256) k_Tred() {
    GDC_WAIT();            // needs g_Tp
    int idx = blockIdx.x * 256 + threadIdx.x;
    const float4* src = (const float4*)g_Tp;
    float4 s = src[idx];
    #pragma unroll
    for (int kc = 1; kc < KSn; kc++) {
        float4 v = src[(size_t)kc * (Bn * Hn * KT / 4) + idx];
        s.x += v.x; s.y += v.y; s.z += v.z; s.w += v.w;
    }
    GDC_LAUNCH();
    ((float4*)g_T)[idx] = s;
}

// ---------------- K7: Ut[b][e][h*8+n] = bf16(((T@Wv_h^T)+z*bv_h)@Wo_h^T) ----
__global__ void __launch_bounds__(256) k_U(const float* __restrict__ Wv,
                                           const float* __restrict__ bv,
                                           const float* __restrict__ Wo) {
    GDC_WAIT();            // needs g_T + g_z (via chain)
    int bh = blockIdx.x, b = bh >> 4, h = bh & 15;
    int eq = blockIdx.y;
    __shared__ float Ts[NT][Hn];
    __shared__ float Ms[NT][64];
    int t = threadIdx.x;
    #pragma unroll
    for (int i = 0; i < 4; i++) {
        int j = t + 256 * i;
        const float* src = g_T + (((size_t)(b * Hn + j)) << 7) + h * 8;
        float4 v0 = *(const float4*)src;
        float4 v1 = *(const float4*)(src + 4);
        Ts[0][j] = v0.x; Ts[1][j] = v0.y; Ts[2][j] = v0.z; Ts[3][j] = v0.w;
        Ts[4][j] = v1.x; Ts[5][j] = v1.y; Ts[6][j] = v1.z; Ts[7][j] = v1.w;
    }
    float zl[NT];
    #pragma unroll
    for (int n = 0; n < NT; n++) zl[n] = g_z[b * KT + h * 8 + n];
    __syncthreads();

    int d = t >> 2, part = t & 3;
    float pn[NT] = {};
    const float* wv = Wv + (size_t)(h * 64 + d) * Hn + part * 256;
    for (int jj = 0; jj < 256; jj += 4) {
        float4 w4 = *(const float4*)(wv + jj);
        int jb = part * 256 + jj;
        #pragma unroll
        for (int n = 0; n < NT; n++) {
            float4 t4 = *(const float4*)&Ts[n][jb];
            pn[n] += w4.x * t4.x + w4.y * t4.y + w4.z * t4.z + w4.w * t4.w;
        }
    }
    #pragma unroll
    for (int n = 0; n < NT; n++) {
        pn[n] += __shfl_xor_sync(0xffffffffu, pn[n], 1);
        pn[n] += __shfl_xor_sync(0xffffffffu, pn[n], 2);
    }
    if (part == 0) {
        float bvd = bv[h * 64 + d];
        #pragma unroll
        for (int n = 0; n < NT; n++) Ms[n][d] = pn[n] + zl[n] * bvd;
    }
    __syncthreads();

    int e = eq * 256 + t;
    float u[NT] = {};
    const float* wo = Wo + (size_t)e * Hn + h * 64;
    #pragma unroll 4
    for (int dd = 0; dd < 64; dd += 4) {
        float4 w4 = *(const float4*)(wo + dd);
        #pragma unroll
        for (int n = 0; n < NT; n++)
            u[n] += w4.x * Ms[n][dd] + w4.y * Ms[n][dd+1]
                  + w4.z * Ms[n][dd+2] + w4.w * Ms[n][dd+3];
    }
    GDC_LAUNCH();
    uint32_t w[4];
    #pragma unroll
    for (int q = 0; q < 4; q++)
        w[q] = bf2u(u[q * 2 + 0], u[q * 2 + 1]);
    *(uint4*)(g_Ut + ((size_t)(b * Hn + e)) * KT + h * 8) = make_uint4(w[0], w[1], w[2], w[3]);
}

// ---------------- K8: out = coef@Ut^T + bo + hs via mma.sync (128x128x128) --
#define PADC 136
__global__ void __launch_bounds__(256) k_comb(const float* __restrict__ bo,
                                              const float* __restrict__ hs,
                                              float* __restrict__ out) {
    GDC_WAIT();            // needs g_Ut + g_z + g_qm (via chain)
    extern __shared__ __align__(16) __nv_bfloat16 smemc[];
    __nv_bfloat16* sA = smemc;                // coef [128][136]
    __nv_bfloat16* sB = smemc + 128 * PADC;   // Ut   [128][136]
    __shared__ float zs[KT];

    int t = threadIdx.x;
    int bn = blockIdx.x, bm = blockIdx.y;
    int b = bm >> 4;
    int sbase = (bm & 15) * 128;

    if (t < KT) zs[t] = g_z[b * KT + t];

    #pragma unroll
    for (int i = 0; i < 8; i++) {
        int idx = t + 256 * i;
        int row = idx >> 4, c = idx & 15;
        *(uint4*)(sB + row * PADC + c * 8) =
            *(const uint4*)(g_Ut + ((size_t)(b * Hn + bn * 128 + row)) * KT + c * 8);
    }
    __syncthreads();   // zs visible

    {
        int m = t >> 1, hbase = (t & 1) * 8;
        int s = sbase + m;
        #pragma unroll
        for (int hh = 0; hh < 8; hh++) {
            int h = hbase + hh;
            float a = g_qm[(size_t)(b * NHn + h) * Sn + s];
            float c[NT], p = 1.f, den = 0.f;
            #pragma unroll
            for (int n = 0; n < NT; n++) {
                c[n] = p * c_invf[n];
                den += c[n] * zs[h * 8 + n];
                p *= a;
            }
            float inv = (den > 0.f) ? 1.f / den : 0.f;
            uint32_t wv[4];
            #pragma unroll
            for (int q = 0; q < 4; q++)
                wv[q] = bf2u(c[q * 2 + 0] * inv, c[q * 2 + 1] * inv);
            *(uint4*)(sA + m * PADC + h * 8) = make_uint4(wv[0], wv[1], wv[2], wv[3]);
        }
    }
    __syncthreads();

    int wid = t >> 5, lane = t & 31;
    int wm = wid >> 1, wn = wid & 1;
    int R = wm * 32, Cb = wn * 64;
    int g = lane >> 2, tg = lane & 3;

    float acc[2][8][4];
    #pragma unroll
    for (int mi = 0; mi < 2; mi++)
        #pragma unroll
        for (int ni = 0; ni < 8; ni++)
            #pragma unroll
            for (int q = 0; q < 4; q++) acc[mi][ni][q] = 0.f;

    #pragma unroll
    for (int ks = 0; ks < 8; ks++) {
        int k0 = ks * 16;
        uint32_t a[2][4];
        #pragma unroll
        for (int mi = 0; mi < 2; mi++) {
            int r0 = R + mi * 16 + g;
            a[mi][0] = *(const uint32_t*)(sA + r0 * PADC + k0 + 2 * tg);
            a[mi][1] = *(const uint32_t*)(sA + (r0 + 8) * PADC + k0 + 2 * tg);
            a[mi][2] = *(const uint32_t*)(sA + r0 * PADC + k0 + 8 + 2 * tg);
            a[mi][3] = *(const uint32_t*)(sA + (r0 + 8) * PADC + k0 + 8 + 2 * tg);
        }
        #pragma unroll
        for (int ni = 0; ni < 8; ni++) {
            int n = Cb + ni * 8 + g;
            uint32_t bb[2];
            bb[0] = *(const uint32_t*)(sB + n * PADC + k0 + 2 * tg);
            bb[1] = *(const uint32_t*)(sB + n * PADC + k0 + 8 + 2 * tg);
            mma16816(acc[0][ni], a[0], bb);
            mma16816(acc[1][ni], a[1], bb);
        }
    }
    GDC_LAUNCH();          // MMA done; epilogue remains

    #pragma unroll
    for (int mi = 0; mi < 2; mi++) {
        #pragma unroll
        for (int half = 0; half < 2; half++) {
            int row = bm * 128 + R + mi * 16 + g + half * 8;
            const float* hp = hs + (size_t)row * Hn;
            float* op = out + (size_t)row * Hn;
            #pragma unroll
            for (int ni = 0; ni < 8; ni++) {
                int col = bn * 128 + Cb + ni * 8 + 2 * tg;
                float2 h2 = *(const float2*)(hp + col);
                float2 b2 = *(const float2*)(bo + col);
                float d0 = acc[mi][ni][half * 2 + 0] + h2.x + b2.x;
                float d1 = acc[mi][ni][half * 2 + 1] + h2.y + b2.y;
                *(float2*)(op + col) = make_float2(d0, d1);
            }
        }
    }
}

// ---------------- K9: LayerNorm, warp-per-row (8 rows/block) ----------------
__global__ void __launch_bounds__(256) k_ln(float* __restrict__ x,
                                            const float* __restrict__ w,
                                            const float* __restrict__ bgam) {
    GDC_WAIT();            // needs out from k_comb
    int wrp = threadIdx.x >> 5, l = threadIdx.x & 31;
    int row = blockIdx.x * 8 + wrp;
    float* p = x + (size_t)row * Hn;
    float4 v[8];
    float s = 0.f, q2 = 0.f;
    #pragma unroll
    for (int i = 0; i < 8; i++) {
        v[i] = *(const float4*)(p + (l + 32 * i) * 4);
        s  += v[i].x + v[i].y + v[i].z + v[i].w;
        q2 += v[i].x*v[i].x + v[i].y*v[i].y + v[i].z*v[i].z + v[i].w*v[i].w;
    }
    #pragma unroll
    for (int off = 16; off; off >>= 1) {
        s  += __shfl_xor_sync(0xffffffffu, s, off);
        q2 += __shfl_xor_sync(0xffffffffu, q2, off);
    }
    float mean = s * (1.f / 1024.f);
    float var = q2 * (1.f / 1024.f) - mean * mean;
    float inv = rsqrtf(var + 1e-5f);
    #pragma unroll
    for (int i = 0; i < 8; i++) {
        int c = (l + 32 * i) * 4;
        float4 w4 = *(const float4*)(w + c);
        float4 g4 = *(const float4*)(bgam + c);
        float4 o;
        o.x = (v[i].x - mean) * inv * w4.x + g4.x;
        o.y = (v[i].y - mean) * inv * w4.y + g4.y;
        o.z = (v[i].z - mean) * inv * w4.z + g4.z;
        o.w = (v[i].w - mean) * inv * w4.w + g4.w;
        *(float4*)(p + c) = o;
    }
}

// ---------------- PDL launch helper ----------------
template <typename F, typename... Args>
static inline void pdl_launch(F func, dim3 grid, dim3 block, size_t smem, Args... args) {
    cudaLaunchAttribute attr[1];
    attr[0].id = cudaLaunchAttributeProgrammaticStreamSerialization;
    attr[0].val.programmaticStreamSerializationAllowed = 1;
    cudaLaunchConfig_t cfg{};
    cfg.gridDim = grid;
    cfg.blockDim = block;
    cfg.dynamicSmemBytes = smem;
    cfg.stream = 0;
    cfg.attrs = attr;
    cfg.numAttrs = 1;
    cudaLaunchKernelEx(&cfg, func, args...);
}

// ---------------- launch: single stream, 9 kernels, PDL-chained -------------
extern "C" void kernel_launch(void* const* d_in, const int* in_sizes, int n_in,
                              void* d_out, int out_size) {
    const float* hs   = (const float*)d_in[0];
    const float* mask = (const float*)d_in[1];
    const float* Wq   = (const float*)d_in[2];
    const float* bq   = (const float*)d_in[3];
    const float* Wk   = (const float*)d_in[4];
    const float* bk   = (const float*)d_in[5];
    const float* Wv   = (const float*)d_in[6];
    const float* bv   = (const float*)d_in[7];
    const float* Wo   = (const float*)d_in[8];
    const float* bo   = (const float*)d_in[9];
    // d_in[10..13]: Wp1,bp1,Wp2,bp2 — dead (one_hot(argmax).sum() == 1)
    const float* lnw  = (const float*)d_in[14];
    const float* lnb  = (const float*)d_in[15];
    float* out = (float*)d_out;

    static int s_attr_done = 0;
    if (!s_attr_done) {
        cudaFuncSetAttribute(k_qkm, cudaFuncAttributeMaxDynamicSharedMemorySize, 74752);
        cudaFuncSetAttribute(k_Tg, cudaFuncAttributeMaxDynamicSharedMemorySize,
                             2 * 128 * PAD * 2);
        cudaFuncSetAttribute(k_comb, cudaFuncAttributeMaxDynamicSharedMemorySize,
                             2 * 128 * PADC * 2);
        s_attr_done = 1;
    }

    pdl_launch(k_bar, dim3(128), dim3(256), 0, Wq, Wk, bq, bk);
    pdl_launch(k_qkm, dim3((Bn * Sn) / 32), dim3(256), 74752, hs, mask);
    pdl_launch(k_tr, dim3(Sn / 64, Hn / 32, Bn), dim3(256), (size_t)0, hs);
    pdl_launch(k_z, dim3(KT / 8, Bn), dim3(256), 0);
    pdl_launch(k_Tg, dim3(Hn / 128, KSn, Bn), dim3(256), 2 * 128 * PAD * 2);
    pdl_launch(k_Tred, dim3((Bn * Hn * KT) / 1024), dim3(256), 0);
    pdl_launch(k_U, dim3(BHn, 4), dim3(256), 0, Wv, bv, Wo);
    pdl_launch(k_comb, dim3(Hn / 128, (Bn * Sn) / 128), dim3(256),
               2 * 128 * PADC * 2, bo, hs, out);
    pdl_launch(k_ln, dim3((Bn * Sn) / 8), dim3(256), 0, out, lnw, lnb);
}

// round 16
// speedup vs baseline: 1.2121x; 1.2121x over previous
#include <cuda_runtime.h>
#include <cuda_bf16.h>
#include <math.h>
#include <stdint.h>

// Problem dims (fixed by setup_inputs)
#define Bn 2
#define Sn 2048
#define Hn 1024
#define NHn 16
#define BHn 32        // Bn*NHn
#define NT 8          // series terms n=0..7
#define KT 128        // NHn*NT — GEMM N/K
#define KSn 8         // k-split chunks for k_Tg (8 x 256)

// ---------------- scratch (device globals; no allocations allowed) ----------
__device__ float g_wbar[32 * Hn];
__device__ float g_bbar[32];
__device__ float g_qm[BHn * Sn];                        // [bh][s]
__device__ __align__(16) __nv_bfloat16 g_Pt[Bn * KT * Sn];   // [b][col][k] bf16
__device__ __align__(16) __nv_bfloat16 g_hsT[(size_t)Bn * Hn * Sn]; // [b][j][k] bf16
__device__ float g_Tp[KSn * Bn * Hn * KT];              // partial T fp32
__device__ float g_T[Bn * Hn * KT];                     // [b][j][col]
__device__ float g_zp[KSn * Bn * KT];                   // z partials (from k_Tg)
__device__ float g_z[Bn * KT];                          // [b][h*8+n]
__device__ __align__(16) __nv_bfloat16 g_Ut[Bn * Hn * KT];   // [b][e][col] bf16

__constant__ float c_invf[NT] = {1.f, 1.f, 0.5f, 1.f/6.f, 1.f/24.f, 1.f/120.f,
                                 1.f/720.f, 1.f/5040.f};

// ---------------- warp-level bf16 MMA (sm_80+ baseline; ok on sm_103) -------
__device__ __forceinline__ void mma16816(float* d, const uint32_t* a, const uint32_t* b) {
    asm volatile(
        "mma.sync.aligned.m16n8k16.row.col.f32.bf16.bf16.f32 "
        "{%0,%1,%2,%3}, {%4,%5,%6,%7}, {%8,%9}, {%0,%1,%2,%3};"
        : "+f"(d[0]), "+f"(d[1]), "+f"(d[2]), "+f"(d[3])
        : "r"(a[0]), "r"(a[1]), "r"(a[2]), "r"(a[3]), "r"(b[0]), "r"(b[1]));
}
__device__ __forceinline__ uint32_t bf2u(float a, float b) {
    __nv_bfloat162 h2;
    h2.x = __float2bfloat16_rn(a);
    h2.y = __float2bfloat16_rn(b);
    return *(uint32_t*)&h2;
}

// ---------------- K1: k_bar ∪ k_tr (independent; branch on blockIdx.x) ------
// blocks [0,128): fold Wq/Wk rows into per-head means
// blocks [128,2176): transpose hs -> g_hsT bf16 [b][j][k]
__global__ void __launch_bounds__(256) k_bartr(const float* __restrict__ Wq,
                                               const float* __restrict__ Wk,
                                               const float* __restrict__ bq,
                                               const float* __restrict__ bk,
                                               const float* __restrict__ hs) {
    __shared__ float sm[64][33];
    int bid = blockIdx.x;
    int t = threadIdx.x;
    if (bid < 128) {
        int idx = bid * 256 + t;
        if (idx < 32 * Hn) {
            int o = idx >> 10, k = idx & (Hn - 1);
            const float* W = (o < 16) ? Wq : Wk;
            int h = o & 15;
            float s = 0.f;
            #pragma unroll 4
            for (int d = 0; d < 64; d++) s += W[(h * 64 + d) * Hn + k];
            g_wbar[o * Hn + k] = s * (1.f / 64.f);
        }
        if (idx < 32) {
            const float* bb = (idx < 16) ? bq : bk;
            int h = idx & 15;
            float s = 0.f;
            for (int d = 0; d < 64; d++) s += bb[h * 64 + d];
            g_bbar[idx] = s * (1.f / 64.f);
        }
        return;
    }
    int r2 = bid - 128;                 // 0..2047
    int k0 = (r2 & 31) * 64;            // Sn/64 index
    int j0 = ((r2 >> 5) & 31) * 32;     // Hn/32 index
    int b = r2 >> 10;                   // batch
    #pragma unroll
    for (int i = 0; i < 2; i++) {
        int idx = t + 256 * i;
        int k = idx >> 3, jq = (idx & 7) * 4;
        float4 v = *(const float4*)&hs[(size_t)(b * Sn + k0 + k) * Hn + j0 + jq];
        sm[k][jq + 0] = v.x; sm[k][jq + 1] = v.y; sm[k][jq + 2] = v.z; sm[k][jq + 3] = v.w;
    }
    __syncthreads();
    int jj = t >> 3, c = t & 7;
    uint32_t w[4];
    #pragma unroll
    for (int q = 0; q < 4; q++)
        w[q] = bf2u(sm[c * 8 + q * 2 + 0][jj], sm[c * 8 + q * 2 + 1][jj]);
    *(uint4*)(g_hsT + ((size_t)(b * Hn + j0 + jj)) * Sn + k0 + c * 8) =
        make_uint4(w[0], w[1], w[2], w[3]);
}

// ---------------- K2: qm/km via mma.sync, chunked K (32 rows/block) ---------
#define QPW 1032
#define QPA 136
__global__ void __launch_bounds__(256) k_qkm(const float* __restrict__ hs,
                                             const float* __restrict__ mask) {
    extern __shared__ __align__(16) char qsm[];
    __nv_bfloat16* sW = (__nv_bfloat16*)qsm;                 // 66048 B
    __nv_bfloat16* sA = (__nv_bfloat16*)(qsm + 66048);       // 8704 B

    int t = threadIdx.x;
    int rb = blockIdx.x * 32;

    {
        int row = t >> 3, cb = (t & 7) * 128;
        const float* wrow = g_wbar + (size_t)row * Hn + cb;
        #pragma unroll
        for (int q = 0; q < 32; q += 2) {
            float4 v0 = *(const float4*)(wrow + q * 4);
            float4 v1 = *(const float4*)(wrow + q * 4 + 4);
            *(uint4*)&sW[row * QPW + cb + q * 4] =
                make_uint4(bf2u(v0.x, v0.y), bf2u(v0.z, v0.w),
                           bf2u(v1.x, v1.y), bf2u(v1.z, v1.w));
        }
    }

    int wid = t >> 5, lane = t & 31, g = lane >> 2, tg = lane & 3;
    int wm = wid & 1, wn = wid >> 1;
    int r0 = wm * 16 + g;
    float acc[4] = {};

    int arow = t >> 3, acb = (t & 7) * 16;
    const float* hrow = hs + (size_t)(rb + arow) * Hn + acb;

    for (int c = 0; c < 8; c++) {
        __syncthreads();
        {
            float4 v0 = *(const float4*)(hrow + c * 128 + 0);
            float4 v1 = *(const float4*)(hrow + c * 128 + 4);
            float4 v2 = *(const float4*)(hrow + c * 128 + 8);
            float4 v3 = *(const float4*)(hrow + c * 128 + 12);
            *(uint4*)&sA[arow * QPA + acb + 0] =
                make_uint4(bf2u(v0.x, v0.y), bf2u(v0.z, v0.w),
                           bf2u(v1.x, v1.y), bf2u(v1.z, v1.w));
            *(uint4*)&sA[arow * QPA + acb + 8] =
                make_uint4(bf2u(v2.x, v2.y), bf2u(v2.z, v2.w),
                           bf2u(v3.x, v3.y), bf2u(v3.z, v3.w));
        }
        __syncthreads();
        #pragma unroll
        for (int ks = 0; ks < 8; ks++) {
            int k0 = ks * 16;
            int kg = c * 128 + k0;
            uint32_t a[4];
            a[0] = *(const uint32_t*)(sA + r0 * QPA + k0 + 2 * tg);
            a[1] = *(const uint32_t*)(sA + (r0 + 8) * QPA + k0 + 2 * tg);
            a[2] = *(const uint32_t*)(sA + r0 * QPA + k0 + 8 + 2 * tg);
            a[3] = *(const uint32_t*)(sA + (r0 + 8) * QPA + k0 + 8 + 2 * tg);
            int n = wn * 8 + g;
            uint32_t bb[2];
            bb[0] = *(const uint32_t*)(sW + n * QPW + kg + 2 * tg);
            bb[1] = *(const uint32_t*)(sW + n * QPW + kg + 8 + 2 * tg);
            mma16816(acc, a, bb);
        }
    }

    int o0 = wn * 8 + 2 * tg;
    #pragma unroll
    for (int rr = 0; rr < 2; rr++) {
        int rg = rb + r0 + rr * 8;
        int b = rg >> 11, s = rg & (Sn - 1);
        float v0 = acc[rr * 2 + 0] + g_bbar[o0];
        float v1 = acc[rr * 2 + 1] + g_bbar[o0 + 1];
        if (o0 < 16) {
            g_qm[(b * NHn + o0) * Sn + s] = v0;
            g_qm[(b * NHn + o0 + 1) * Sn + s] = v1;
        } else {
            float mk = (mask[b * Sn + s] > 0.f) ? 1.f : 0.f;
            int h0 = o0 - 16;
            __nv_bfloat16* d0 = g_Pt + (size_t)(b * KT + h0 * 8) * Sn + s;
            __nv_bfloat16* d1 = g_Pt + (size_t)(b * KT + (h0 + 1) * 8) * Sn + s;
            float p0 = mk, p1 = mk;
            #pragma unroll
            for (int n = 0; n < NT; n++) {
                d0[(size_t)n * Sn] = __float2bfloat16_rn(p0);
                d1[(size_t)n * Sn] = __float2bfloat16_rn(p1);
                p0 *= v0; p1 *= v1;
            }
        }
    }
}

// ---------------- K3: T-GEMM via mma.sync + z partials (128x128x256) --------
// jt==0 blocks column-sum their staged Pt tile into g_zp (~0.2us, hidden).
#define PAD 264
__global__ void __launch_bounds__(256) k_Tg() {
    extern __shared__ __align__(16) __nv_bfloat16 smem[];
    __nv_bfloat16* sA = smem;               // [128][264]
    __nv_bfloat16* sB = smem + 128 * PAD;   // [128][264]
    int t = threadIdx.x;
    int jt = blockIdx.x, kc = blockIdx.y, b = blockIdx.z;
    int k0g = kc * 256;

    const __nv_bfloat16* Asrc = g_hsT + ((size_t)(b * Hn + jt * 128)) * Sn + k0g;
    const __nv_bfloat16* Bsrc = g_Pt + ((size_t)(b * KT)) * Sn + k0g;
    #pragma unroll
    for (int i = 0; i < 16; i++) {
        int idx = t + 256 * i;
        int m = idx >> 5, c = idx & 31;
        *(uint4*)(sA + m * PAD + c * 8) = *(const uint4*)(Asrc + (size_t)m * Sn + c * 8);
        *(uint4*)(sB + m * PAD + c * 8) = *(const uint4*)(Bsrc + (size_t)m * Sn + c * 8);
    }
    __syncthreads();

    if (jt == 0) {
        int col = t >> 1, half = t & 1;
        const __nv_bfloat16* srow = sB + col * PAD + half * 128;
        float s = 0.f;
        #pragma unroll
        for (int i = 0; i < 16; i++) {
            uint4 v = *(const uint4*)(srow + i * 8);
            uint32_t u[4] = {v.x, v.y, v.z, v.w};
            #pragma unroll
            for (int q = 0; q < 4; q++) {
                float2 f = __bfloat1622float2(*(__nv_bfloat162*)&u[q]);
                s += f.x + f.y;
            }
        }
        s += __shfl_xor_sync(0xffffffffu, s, 1);
        if (half == 0) g_zp[(kc * Bn + b) * KT + col] = s;
    }

    int wid = t >> 5, lane = t & 31;
    int wm = wid >> 1, wn = wid & 1;
    int R = wm * 32, Cb = wn * 64;
    int g = lane >> 2, tg = lane & 3;

    float acc[2][8][4];
    #pragma unroll
    for (int mi = 0; mi < 2; mi++)
        #pragma unroll
        for (int ni = 0; ni < 8; ni++)
            #pragma unroll
            for (int q = 0; q < 4; q++) acc[mi][ni][q] = 0.f;

    #pragma unroll 4
    for (int ks = 0; ks < 16; ks++) {
        int k0 = ks * 16;
        uint32_t a[2][4];
        #pragma unroll
        for (int mi = 0; mi < 2; mi++) {
            int r0 = R + mi * 16 + g;
            a[mi][0] = *(const uint32_t*)(sA + r0 * PAD + k0 + 2 * tg);
            a[mi][1] = *(const uint32_t*)(sA + (r0 + 8) * PAD + k0 + 2 * tg);
            a[mi][2] = *(const uint32_t*)(sA + r0 * PAD + k0 + 8 + 2 * tg);
            a[mi][3] = *(const uint32_t*)(sA + (r0 + 8) * PAD + k0 + 8 + 2 * tg);
        }
        #pragma unroll
        for (int ni = 0; ni < 8; ni++) {
            int n = Cb + ni * 8 + g;
            uint32_t bb[2];
            bb[0] = *(const uint32_t*)(sB + n * PAD + k0 + 2 * tg);
            bb[1] = *(const uint32_t*)(sB + n * PAD + k0 + 8 + 2 * tg);
            mma16816(acc[0][ni], a[0], bb);
            mma16816(acc[1][ni], a[1], bb);
        }
    }

    #pragma unroll
    for (int mi = 0; mi < 2; mi++) {
        int j = jt * 128 + R + mi * 16 + g;
        float* base = g_Tp + ((size_t)((kc * Bn + b) * Hn + j)) * KT;
        #pragma unroll
        for (int ni = 0; ni < 8; ni++) {
            int col = Cb + ni * 8 + 2 * tg;
            *(float2*)(base + col) = make_float2(acc[mi][ni][0], acc[mi][ni][1]);
            *(float2*)(base + 8 * KT + col) = make_float2(acc[mi][ni][2], acc[mi][ni][3]);
        }
    }
}

// ---------------- K4: reduce T partials + z partials (deterministic) --------
__global__ void __launch_bounds__(256) k_Tred() {
    int idx = blockIdx.x * 256 + threadIdx.x;
    const float4* src = (const float4*)g_Tp;
    float4 s = src[idx];
    #pragma unroll
    for (int kc = 1; kc < KSn; kc++) {
        float4 v = src[(size_t)kc * (Bn * Hn * KT / 4) + idx];
        s.x += v.x; s.y += v.y; s.z += v.z; s.w += v.w;
    }
    ((float4*)g_T)[idx] = s;

    if (blockIdx.x == 0) {      // fold z partials (Bn*KT == 256 threads)
        int tt = threadIdx.x;
        int b = tt >> 7, col = tt & 127;
        float z = 0.f;
        #pragma unroll
        for (int kc = 0; kc < KSn; kc++) z += g_zp[(kc * Bn + b) * KT + col];
        g_z[b * KT + col] = z;
    }
}

// ---------------- K5: Ut[b][e][h*8+n] = bf16(((T@Wv_h^T)+z*bv_h)@Wo_h^T) ----
__global__ void __launch_bounds__(256) k_U(const float* __restrict__ Wv,
                                           const float* __restrict__ bv,
                                           const float* __restrict__ Wo) {
    int bh = blockIdx.x, b = bh >> 4, h = bh & 15;
    int eq = blockIdx.y;
    __shared__ float Ts[NT][Hn];
    __shared__ float Ms[NT][64];
    int t = threadIdx.x;
    #pragma unroll
    for (int i = 0; i < 4; i++) {
        int j = t + 256 * i;
        const float* src = g_T + (((size_t)(b * Hn + j)) << 7) + h * 8;
        float4 v0 = *(const float4*)src;
        float4 v1 = *(const float4*)(src + 4);
        Ts[0][j] = v0.x; Ts[1][j] = v0.y; Ts[2][j] = v0.z; Ts[3][j] = v0.w;
        Ts[4][j] = v1.x; Ts[5][j] = v1.y; Ts[6][j] = v1.z; Ts[7][j] = v1.w;
    }
    float zl[NT];
    #pragma unroll
    for (int n = 0; n < NT; n++) zl[n] = g_z[b * KT + h * 8 + n];
    __syncthreads();

    int d = t >> 2, part = t & 3;
    float pn[NT] = {};
    const float* wv = Wv + (size_t)(h * 64 + d) * Hn + part * 256;
    for (int jj = 0; jj < 256; jj += 4) {
        float4 w4 = *(const float4*)(wv + jj);
        int jb = part * 256 + jj;
        #pragma unroll
        for (int n = 0; n < NT; n++) {
            float4 t4 = *(const float4*)&Ts[n][jb];
            pn[n] += w4.x * t4.x + w4.y * t4.y + w4.z * t4.z + w4.w * t4.w;
        }
    }
    #pragma unroll
    for (int n = 0; n < NT; n++) {
        pn[n] += __shfl_xor_sync(0xffffffffu, pn[n], 1);
        pn[n] += __shfl_xor_sync(0xffffffffu, pn[n], 2);
    }
    if (part == 0) {
        float bvd = bv[h * 64 + d];
        #pragma unroll
        for (int n = 0; n < NT; n++) Ms[n][d] = pn[n] + zl[n] * bvd;
    }
    __syncthreads();

    int e = eq * 256 + t;
    float u[NT] = {};
    const float* wo = Wo + (size_t)e * Hn + h * 64;
    #pragma unroll 4
    for (int dd = 0; dd < 64; dd += 4) {
        float4 w4 = *(const float4*)(wo + dd);
        #pragma unroll
        for (int n = 0; n < NT; n++)
            u[n] += w4.x * Ms[n][dd] + w4.y * Ms[n][dd+1]
                  + w4.z * Ms[n][dd+2] + w4.w * Ms[n][dd+3];
    }
    uint32_t w[4];
    #pragma unroll
    for (int q = 0; q < 4; q++)
        w[q] = bf2u(u[q * 2 + 0], u[q * 2 + 1]);
    *(uint4*)(g_Ut + ((size_t)(b * Hn + e)) * KT + h * 8) = make_uint4(w[0], w[1], w[2], w[3]);
}

// ---------------- K6: out = coef@Ut^T + bo + hs via mma.sync (128x128x128) --
#define PADC 136
__global__ void __launch_bounds__(256) k_comb(const float* __restrict__ bo,
                                              const float* __restrict__ hs,
                                              float* __restrict__ out) {
    extern __shared__ __align__(16) __nv_bfloat16 smemc[];
    __nv_bfloat16* sA = smemc;                // coef [128][136]
    __nv_bfloat16* sB = smemc + 128 * PADC;   // Ut   [128][136]
    __shared__ float zs[KT];

    int t = threadIdx.x;
    int bn = blockIdx.x, bm = blockIdx.y;
    int b = bm >> 4;
    int sbase = (bm & 15) * 128;

    if (t < KT) zs[t] = g_z[b * KT + t];

    #pragma unroll
    for (int i = 0; i < 8; i++) {
        int idx = t + 256 * i;
        int row = idx >> 4, c = idx & 15;
        *(uint4*)(sB + row * PADC + c * 8) =
            *(const uint4*)(g_Ut + ((size_t)(b * Hn + bn * 128 + row)) * KT + c * 8);
    }
    __syncthreads();   // zs visible

    {
        int m = t >> 1, hbase = (t & 1) * 8;
        int s = sbase + m;
        #pragma unroll
        for (int hh = 0; hh < 8; hh++) {
            int h = hbase + hh;
            float a = g_qm[(size_t)(b * NHn + h) * Sn + s];
            float c[NT], p = 1.f, den = 0.f;
            #pragma unroll
            for (int n = 0; n < NT; n++) {
                c[n] = p * c_invf[n];
                den += c[n] * zs[h * 8 + n];
                p *= a;
            }
            float inv = (den > 0.f) ? 1.f / den : 0.f;
            uint32_t wv[4];
            #pragma unroll
            for (int q = 0; q < 4; q++)
                wv[q] = bf2u(c[q * 2 + 0] * inv, c[q * 2 + 1] * inv);
            *(uint4*)(sA + m * PADC + h * 8) = make_uint4(wv[0], wv[1], wv[2], wv[3]);
        }
    }
    __syncthreads();

    int wid = t >> 5, lane = t & 31;
    int wm = wid >> 1, wn = wid & 1;
    int R = wm * 32, Cb = wn * 64;
    int g = lane >> 2, tg = lane & 3;

    float acc[2][8][4];
    #pragma unroll
    for (int mi = 0; mi < 2; mi++)
        #pragma unroll
        for (int ni = 0; ni < 8; ni++)
            #pragma unroll
            for (int q = 0; q < 4; q++) acc[mi][ni][q] = 0.f;

    #pragma unroll
    for (int ks = 0; ks < 8; ks++) {
        int k0 = ks * 16;
        uint32_t a[2][4];
        #pragma unroll
        for (int mi = 0; mi < 2; mi++) {
            int r0 = R + mi * 16 + g;
            a[mi][0] = *(const uint32_t*)(sA + r0 * PADC + k0 + 2 * tg);
            a[mi][1] = *(const uint32_t*)(sA + (r0 + 8) * PADC + k0 + 2 * tg);
            a[mi][2] = *(const uint32_t*)(sA + r0 * PADC + k0 + 8 + 2 * tg);
            a[mi][3] = *(const uint32_t*)(sA + (r0 + 8) * PADC + k0 + 8 + 2 * tg);
        }
        #pragma unroll
        for (int ni = 0; ni < 8; ni++) {
            int n = Cb + ni * 8 + g;
            uint32_t bb[2];
            bb[0] = *(const uint32_t*)(sB + n * PADC + k0 + 2 * tg);
            bb[1] = *(const uint32_t*)(sB + n * PADC + k0 + 8 + 2 * tg);
            mma16816(acc[0][ni], a[0], bb);
            mma16816(acc[1][ni], a[1], bb);
        }
    }

    #pragma unroll
    for (int mi = 0; mi < 2; mi++) {
        #pragma unroll
        for (int half = 0; half < 2; half++) {
            int row = bm * 128 + R + mi * 16 + g + half * 8;
            const float* hp = hs + (size_t)row * Hn;
            float* op = out + (size_t)row * Hn;
            #pragma unroll
            for (int ni = 0; ni < 8; ni++) {
                int col = bn * 128 + Cb + ni * 8 + 2 * tg;
                float2 h2 = *(const float2*)(hp + col);
                float2 b2 = *(const float2*)(bo + col);
                float d0 = acc[mi][ni][half * 2 + 0] + h2.x + b2.x;
                float d1 = acc[mi][ni][half * 2 + 1] + h2.y + b2.y;
                *(float2*)(op + col) = make_float2(d0, d1);
            }
        }
    }
}

// ---------------- K7: LayerNorm, warp-per-row (8 rows/block) ----------------
__global__ void __launch_bounds__(256) k_ln(float* __restrict__ x,
                                            const float* __restrict__ w,
                                            const float* __restrict__ bgam) {
    int wrp = threadIdx.x >> 5, l = threadIdx.x & 31;
    int row = blockIdx.x * 8 + wrp;
    float* p = x + (size_t)row * Hn;
    float4 v[8];
    float s = 0.f, q2 = 0.f;
    #pragma unroll
    for (int i = 0; i < 8; i++) {
        v[i] = *(const float4*)(p + (l + 32 * i) * 4);
        s  += v[i].x + v[i].y + v[i].z + v[i].w;
        q2 += v[i].x*v[i].x + v[i].y*v[i].y + v[i].z*v[i].z + v[i].w*v[i].w;
    }
    #pragma unroll
    for (int off = 16; off; off >>= 1) {
        s  += __shfl_xor_sync(0xffffffffu, s, off);
        q2 += __shfl_xor_sync(0xffffffffu, q2, off);
    }
    float mean = s * (1.f / 1024.f);
    float var = q2 * (1.f / 1024.f) - mean * mean;
    float inv = rsqrtf(var + 1e-5f);
    #pragma unroll
    for (int i = 0; i < 8; i++) {
        int c = (l + 32 * i) * 4;
        float4 w4 = *(const float4*)(w + c);
        float4 g4 = *(const float4*)(bgam + c);
        float4 o;
        o.x = (v[i].x - mean) * inv * w4.x + g4.x;
        o.y = (v[i].y - mean) * inv * w4.y + g4.y;
        o.z = (v[i].z - mean) * inv * w4.z + g4.z;
        o.w = (v[i].w - mean) * inv * w4.w + g4.w;
        *(float4*)(p + c) = o;
    }
}

// ---------------- launch: single stream, 7 kernels ----------------
extern "C" void kernel_launch(void* const* d_in, const int* in_sizes, int n_in,
                              void* d_out, int out_size) {
    const float* hs   = (const float*)d_in[0];
    const float* mask = (const float*)d_in[1];
    const float* Wq   = (const float*)d_in[2];
    const float* bq   = (const float*)d_in[3];
    const float* Wk   = (const float*)d_in[4];
    const float* bk   = (const float*)d_in[5];
    const float* Wv   = (const float*)d_in[6];
    const float* bv   = (const float*)d_in[7];
    const float* Wo   = (const float*)d_in[8];
    const float* bo   = (const float*)d_in[9];
    // d_in[10..13]: Wp1,bp1,Wp2,bp2 — dead (one_hot(argmax).sum() == 1)
    const float* lnw  = (const float*)d_in[14];
    const float* lnb  = (const float*)d_in[15];
    float* out = (float*)d_out;

    static int s_attr_done = 0;
    if (!s_attr_done) {
        cudaFuncSetAttribute(k_qkm, cudaFuncAttributeMaxDynamicSharedMemorySize, 74752);
        cudaFuncSetAttribute(k_Tg, cudaFuncAttributeMaxDynamicSharedMemorySize,
                             2 * 128 * PAD * 2);
        cudaFuncSetAttribute(k_comb, cudaFuncAttributeMaxDynamicSharedMemorySize,
                             2 * 128 * PADC * 2);
        s_attr_done = 1;
    }

    k_bartr<<<128 + 2048, 256>>>(Wq, Wk, bq, bk, hs);
    k_qkm<<<(Bn * Sn) / 32, 256, 74752>>>(hs, mask);
    k_Tg<<<dim3(Hn / 128, KSn, Bn), 256, 2 * 128 * PAD * 2>>>();
    k_Tred<<<(Bn * Hn * KT) / 1024, 256>>>();
    k_U<<<dim3(BHn, 4), 256>>>(Wv, bv, Wo);
    k_comb<<<dim3(Hn / 128, (Bn * Sn) / 128), 256, 2 * 128 * PADC * 2>>>(bo, hs, out);
    k_ln<<<(Bn * Sn) / 8, 256>>>(out, lnw, lnb);
}

// round 17
// speedup vs baseline: 1.2662x; 1.0446x over previous
#include <cuda_runtime.h>
#include <cuda_bf16.h>
#include <math.h>
#include <stdint.h>

// Problem dims (fixed by setup_inputs)
#define Bn 2
#define Sn 2048
#define Hn 1024
#define NHn 16
#define BHn 32        // Bn*NHn
#define NT 8          // series terms n=0..7
#define KT 128        // NHn*KT/16 — GEMM N/K
#define KSn 8         // k-split chunks for k_Tg (8 x 256)

// ---------------- scratch (device globals; no allocations allowed) ----------
__device__ float g_wbar[32 * Hn];
__device__ float g_bbar[32];
__device__ float g_qm[BHn * Sn];                        // [bh][s]
__device__ __align__(16) __nv_bfloat16 g_Pt[Bn * KT * Sn];   // [b][col][k] bf16
__device__ __align__(16) __nv_bfloat16 g_hsT[(size_t)Bn * Hn * Sn]; // [b][j][k] bf16
__device__ float g_Tp[KSn * Bn * Hn * KT];              // partial T fp32
__device__ float g_T[Bn * Hn * KT];                     // [b][j][col]
__device__ float g_zp[KSn * Bn * KT];                   // z partials (from k_Tg)
__device__ float g_z[Bn * KT];                          // [b][h*8+n]
__device__ __align__(16) __nv_bfloat16 g_Ut[Bn * Hn * KT];   // [b][e][col] bf16

__constant__ float c_invf[NT] = {1.f, 1.f, 0.5f, 1.f/6.f, 1.f/24.f, 1.f/120.f,
                                 1.f/720.f, 1.f/5040.f};

// ---------------- warp-level bf16 MMA (sm_80+ baseline; ok on sm_103) -------
__device__ __forceinline__ void mma16816(float* d, const uint32_t* a, const uint32_t* b) {
    asm volatile(
        "mma.sync.aligned.m16n8k16.row.col.f32.bf16.bf16.f32 "
        "{%0,%1,%2,%3}, {%4,%5,%6,%7}, {%8,%9}, {%0,%1,%2,%3};"
        : "+f"(d[0]), "+f"(d[1]), "+f"(d[2]), "+f"(d[3])
        : "r"(a[0]), "r"(a[1]), "r"(a[2]), "r"(a[3]), "r"(b[0]), "r"(b[1]));
}
__device__ __forceinline__ uint32_t bf2u(float a, float b) {
    __nv_bfloat162 h2;
    h2.x = __float2bfloat16_rn(a);
    h2.y = __float2bfloat16_rn(b);
    return *(uint32_t*)&h2;
}

// ---------------- K1: k_bar ∪ k_tr (independent; branch on blockIdx.x) ------
__global__ void __launch_bounds__(256) k_bartr(const float* __restrict__ Wq,
                                               const float* __restrict__ Wk,
                                               const float* __restrict__ bq,
                                               const float* __restrict__ bk,
                                               const float* __restrict__ hs) {
    __shared__ float sm[64][33];
    int bid = blockIdx.x;
    int t = threadIdx.x;
    if (bid < 128) {
        int idx = bid * 256 + t;
        if (idx < 32 * Hn) {
            int o = idx >> 10, k = idx & (Hn - 1);
            const float* W = (o < 16) ? Wq : Wk;
            int h = o & 15;
            float s = 0.f;
            #pragma unroll 4
            for (int d = 0; d < 64; d++) s += W[(h * 64 + d) * Hn + k];
            g_wbar[o * Hn + k] = s * (1.f / 64.f);
        }
        if (idx < 32) {
            const float* bb = (idx < 16) ? bq : bk;
            int h = idx & 15;
            float s = 0.f;
            for (int d = 0; d < 64; d++) s += bb[h * 64 + d];
            g_bbar[idx] = s * (1.f / 64.f);
        }
        return;
    }
    int r2 = bid - 128;
    int k0 = (r2 & 31) * 64;
    int j0 = ((r2 >> 5) & 31) * 32;
    int b = r2 >> 10;
    #pragma unroll
    for (int i = 0; i < 2; i++) {
        int idx = t + 256 * i;
        int k = idx >> 3, jq = (idx & 7) * 4;
        float4 v = *(const float4*)&hs[(size_t)(b * Sn + k0 + k) * Hn + j0 + jq];
        sm[k][jq + 0] = v.x; sm[k][jq + 1] = v.y; sm[k][jq + 2] = v.z; sm[k][jq + 3] = v.w;
    }
    __syncthreads();
    int jj = t >> 3, c = t & 7;
    uint32_t w[4];
    #pragma unroll
    for (int q = 0; q < 4; q++)
        w[q] = bf2u(sm[c * 8 + q * 2 + 0][jj], sm[c * 8 + q * 2 + 1][jj]);
    *(uint4*)(g_hsT + ((size_t)(b * Hn + j0 + jj)) * Sn + k0 + c * 8) =
        make_uint4(w[0], w[1], w[2], w[3]);
}

// ---------------- K2: qm/km via mma.sync, double-buffered K chunks ----------
#define QPW 1032
#define QPA 136
__global__ void __launch_bounds__(256) k_qkm(const float* __restrict__ hs,
                                             const float* __restrict__ mask) {
    extern __shared__ __align__(16) char qsm[];
    __nv_bfloat16* sW = (__nv_bfloat16*)qsm;                   // 66048 B
    __nv_bfloat16* sA0 = (__nv_bfloat16*)(qsm + 66048);        // 8704 B
    __nv_bfloat16* sA1 = (__nv_bfloat16*)(qsm + 66048 + 8704); // 8704 B

    int t = threadIdx.x;
    int rb = blockIdx.x * 32;

    {   // stage wbar (fp32 -> bf16), whole 32x1024 once
        int row = t >> 3, cb = (t & 7) * 128;
        const float* wrow = g_wbar + (size_t)row * Hn + cb;
        #pragma unroll
        for (int q = 0; q < 32; q += 2) {
            float4 v0 = *(const float4*)(wrow + q * 4);
            float4 v1 = *(const float4*)(wrow + q * 4 + 4);
            *(uint4*)&sW[row * QPW + cb + q * 4] =
                make_uint4(bf2u(v0.x, v0.y), bf2u(v0.z, v0.w),
                           bf2u(v1.x, v1.y), bf2u(v1.z, v1.w));
        }
    }

    int wid = t >> 5, lane = t & 31, g = lane >> 2, tg = lane & 3;
    int wm = wid & 1, wn = wid >> 1;
    int r0 = wm * 16 + g;
    float acc[4] = {};

    int arow = t >> 3, acb = (t & 7) * 16;
    const float* hrow = hs + (size_t)(rb + arow) * Hn + acb;

    {   // stage chunk 0 into sA0
        float4 v0 = *(const float4*)(hrow + 0);
        float4 v1 = *(const float4*)(hrow + 4);
        float4 v2 = *(const float4*)(hrow + 8);
        float4 v3 = *(const float4*)(hrow + 12);
        *(uint4*)&sA0[arow * QPA + acb + 0] =
            make_uint4(bf2u(v0.x, v0.y), bf2u(v0.z, v0.w),
                       bf2u(v1.x, v1.y), bf2u(v1.z, v1.w));
        *(uint4*)&sA0[arow * QPA + acb + 8] =
            make_uint4(bf2u(v2.x, v2.y), bf2u(v2.z, v2.w),
                       bf2u(v3.x, v3.y), bf2u(v3.z, v3.w));
    }
    __syncthreads();   // sW + chunk0 ready

    #pragma unroll
    for (int c = 0; c < 8; c++) {
        __nv_bfloat16* bufc = (c & 1) ? sA1 : sA0;
        __nv_bfloat16* bufn = (c & 1) ? sA0 : sA1;
        bool more = (c < 7);
        float4 p0, p1, p2, p3;
        if (more) {
            p0 = *(const float4*)(hrow + (c + 1) * 128 + 0);
            p1 = *(const float4*)(hrow + (c + 1) * 128 + 4);
            p2 = *(const float4*)(hrow + (c + 1) * 128 + 8);
            p3 = *(const float4*)(hrow + (c + 1) * 128 + 12);
        }
        #pragma unroll
        for (int ks = 0; ks < 8; ks++) {
            int k0 = ks * 16;
            int kg = c * 128 + k0;
            uint32_t a[4];
            a[0] = *(const uint32_t*)(bufc + r0 * QPA + k0 + 2 * tg);
            a[1] = *(const uint32_t*)(bufc + (r0 + 8) * QPA + k0 + 2 * tg);
            a[2] = *(const uint32_t*)(bufc + r0 * QPA + k0 + 8 + 2 * tg);
            a[3] = *(const uint32_t*)(bufc + (r0 + 8) * QPA + k0 + 8 + 2 * tg);
            int n = wn * 8 + g;
            uint32_t bb[2];
            bb[0] = *(const uint32_t*)(sW + n * QPW + kg + 2 * tg);
            bb[1] = *(const uint32_t*)(sW + n * QPW + kg + 8 + 2 * tg);
            mma16816(acc, a, bb);
        }
        if (more) {
            *(uint4*)&bufn[arow * QPA + acb + 0] =
                make_uint4(bf2u(p0.x, p0.y), bf2u(p0.z, p0.w),
                           bf2u(p1.x, p1.y), bf2u(p1.z, p1.w));
            *(uint4*)&bufn[arow * QPA + acb + 8] =
                make_uint4(bf2u(p2.x, p2.y), bf2u(p2.z, p2.w),
                           bf2u(p3.x, p3.y), bf2u(p3.z, p3.w));
        }
        __syncthreads();
    }

    int o0 = wn * 8 + 2 * tg;
    #pragma unroll
    for (int rr = 0; rr < 2; rr++) {
        int rg = rb + r0 + rr * 8;
        int b = rg >> 11, s = rg & (Sn - 1);
        float v0 = acc[rr * 2 + 0] + g_bbar[o0];
        float v1 = acc[rr * 2 + 1] + g_bbar[o0 + 1];
        if (o0 < 16) {
            g_qm[(b * NHn + o0) * Sn + s] = v0;
            g_qm[(b * NHn + o0 + 1) * Sn + s] = v1;
        } else {
            float mk = (mask[b * Sn + s] > 0.f) ? 1.f : 0.f;
            int h0 = o0 - 16;
            __nv_bfloat16* d0 = g_Pt + (size_t)(b * KT + h0 * 8) * Sn + s;
            __nv_bfloat16* d1 = g_Pt + (size_t)(b * KT + (h0 + 1) * 8) * Sn + s;
            float p0 = mk, p1 = mk;
            #pragma unroll
            for (int n = 0; n < NT; n++) {
                d0[(size_t)n * Sn] = __float2bfloat16_rn(p0);
                d1[(size_t)n * Sn] = __float2bfloat16_rn(p1);
                p0 *= v0; p1 *= v1;
            }
        }
    }
}

// ---------------- K3: T-GEMM, double-buffered 64-k slabs + z partials -------
// row pitch 72 bf16 = 144 B ≡ 4 words mod 32 banks (same pattern as old 264)
#define PAD2 72
__global__ void __launch_bounds__(256) k_Tg() {
    extern __shared__ __align__(16) __nv_bfloat16 smem[];
    __nv_bfloat16* bufA[2] = { smem, smem + 128 * PAD2 };
    __nv_bfloat16* bufB[2] = { smem + 2 * 128 * PAD2, smem + 3 * 128 * PAD2 };
    int t = threadIdx.x;
    int jt = blockIdx.x, kc = blockIdx.y, b = blockIdx.z;
    int k0g = kc * 256;

    const __nv_bfloat16* Asrc = g_hsT + ((size_t)(b * Hn + jt * 128)) * Sn + k0g;
    const __nv_bfloat16* Bsrc = g_Pt + ((size_t)(b * KT)) * Sn + k0g;

    int lm[4], lc[4];
    #pragma unroll
    for (int i = 0; i < 4; i++) {
        int idx = t + 256 * i;
        lm[i] = idx >> 3;
        lc[i] = (idx & 7) * 8;
    }
    // stage slab 0
    #pragma unroll
    for (int i = 0; i < 4; i++) {
        *(uint4*)(bufA[0] + lm[i] * PAD2 + lc[i]) =
            *(const uint4*)(Asrc + (size_t)lm[i] * Sn + lc[i]);
        *(uint4*)(bufB[0] + lm[i] * PAD2 + lc[i]) =
            *(const uint4*)(Bsrc + (size_t)lm[i] * Sn + lc[i]);
    }
    __syncthreads();

    int wid = t >> 5, lane = t & 31;
    int wm = wid >> 1, wn = wid & 1;
    int R = wm * 32, Cb = wn * 64;
    int g = lane >> 2, tg = lane & 3;

    float acc[2][8][4];
    #pragma unroll
    for (int mi = 0; mi < 2; mi++)
        #pragma unroll
        for (int ni = 0; ni < 8; ni++)
            #pragma unroll
            for (int q = 0; q < 4; q++) acc[mi][ni][q] = 0.f;

    float zacc = 0.f;
    int zcol = t >> 1, zhalf = t & 1;

    #pragma unroll
    for (int sl = 0; sl < 4; sl++) {
        int cur = sl & 1;
        bool more = (sl < 3);
        uint4 pa[4], pb[4];
        if (more) {
            int off = (sl + 1) * 64;
            #pragma unroll
            for (int i = 0; i < 4; i++) {
                pa[i] = *(const uint4*)(Asrc + (size_t)lm[i] * Sn + off + lc[i]);
                pb[i] = *(const uint4*)(Bsrc + (size_t)lm[i] * Sn + off + lc[i]);
            }
        }
        if (jt == 0) {     // z partial: 32 k of this slab per thread
            const __nv_bfloat16* srow = bufB[cur] + zcol * PAD2 + zhalf * 32;
            #pragma unroll
            for (int i = 0; i < 4; i++) {
                uint4 v = *(const uint4*)(srow + i * 8);
                uint32_t u[4] = {v.x, v.y, v.z, v.w};
                #pragma unroll
                for (int q = 0; q < 4; q++) {
                    float2 f = __bfloat1622float2(*(__nv_bfloat162*)&u[q]);
                    zacc += f.x + f.y;
                }
            }
        }
        #pragma unroll
        for (int ks = 0; ks < 4; ks++) {
            int k0 = ks * 16;
            uint32_t a[2][4];
            #pragma unroll
            for (int mi = 0; mi < 2; mi++) {
                int r0 = R + mi * 16 + g;
                a[mi][0] = *(const uint32_t*)(bufA[cur] + r0 * PAD2 + k0 + 2 * tg);
                a[mi][1] = *(const uint32_t*)(bufA[cur] + (r0 + 8) * PAD2 + k0 + 2 * tg);
                a[mi][2] = *(const uint32_t*)(bufA[cur] + r0 * PAD2 + k0 + 8 + 2 * tg);
                a[mi][3] = *(const uint32_t*)(bufA[cur] + (r0 + 8) * PAD2 + k0 + 8 + 2 * tg);
            }
            #pragma unroll
            for (int ni = 0; ni < 8; ni++) {
                int n = Cb + ni * 8 + g;
                uint32_t bb[2];
                bb[0] = *(const uint32_t*)(bufB[cur] + n * PAD2 + k0 + 2 * tg);
                bb[1] = *(const uint32_t*)(bufB[cur] + n * PAD2 + k0 + 8 + 2 * tg);
                mma16816(acc[0][ni], a[0], bb);
                mma16816(acc[1][ni], a[1], bb);
            }
        }
        if (more) {
            #pragma unroll
            for (int i = 0; i < 4; i++) {
                *(uint4*)(bufA[cur ^ 1] + lm[i] * PAD2 + lc[i]) = pa[i];
                *(uint4*)(bufB[cur ^ 1] + lm[i] * PAD2 + lc[i]) = pb[i];
            }
        }
        __syncthreads();
    }

    if (jt == 0) {
        zacc += __shfl_xor_sync(0xffffffffu, zacc, 1);
        if (zhalf == 0) g_zp[(kc * Bn + b) * KT + zcol] = zacc;
    }

    #pragma unroll
    for (int mi = 0; mi < 2; mi++) {
        int j = jt * 128 + R + mi * 16 + g;
        float* base = g_Tp + ((size_t)((kc * Bn + b) * Hn + j)) * KT;
        #pragma unroll
        for (int ni = 0; ni < 8; ni++) {
            int col = Cb + ni * 8 + 2 * tg;
            *(float2*)(base + col) = make_float2(acc[mi][ni][0], acc[mi][ni][1]);
            *(float2*)(base + 8 * KT + col) = make_float2(acc[mi][ni][2], acc[mi][ni][3]);
        }
    }
}

// ---------------- K4: reduce T partials + z partials (deterministic) --------
__global__ void __launch_bounds__(256) k_Tred() {
    int idx = blockIdx.x * 256 + threadIdx.x;
    const float4* src = (const float4*)g_Tp;
    float4 s = src[idx];
    #pragma unroll
    for (int kc = 1; kc < KSn; kc++) {
        float4 v = src[(size_t)kc * (Bn * Hn * KT / 4) + idx];
        s.x += v.x; s.y += v.y; s.z += v.z; s.w += v.w;
    }
    ((float4*)g_T)[idx] = s;

    if (blockIdx.x == 0) {
        int tt = threadIdx.x;
        int b = tt >> 7, col = tt & 127;
        float z = 0.f;
        #pragma unroll
        for (int kc = 0; kc < KSn; kc++) z += g_zp[(kc * Bn + b) * KT + col];
        g_z[b * KT + col] = z;
    }
}

// ---------------- K5: Ut[b][e][h*8+n] = bf16(((T@Wv_h^T)+z*bv_h)@Wo_h^T) ----
__global__ void __launch_bounds__(256) k_U(const float* __restrict__ Wv,
                                           const float* __restrict__ bv,
                                           const float* __restrict__ Wo) {
    int bh = blockIdx.x, b = bh >> 4, h = bh & 15;
    int eq = blockIdx.y;
    __shared__ float Ts[NT][Hn];
    __shared__ float Ms[NT][64];
    int t = threadIdx.x;
    #pragma unroll
    for (int i = 0; i < 4; i++) {
        int j = t + 256 * i;
        const float* src = g_T + (((size_t)(b * Hn + j)) << 7) + h * 8;
        float4 v0 = *(const float4*)src;
        float4 v1 = *(const float4*)(src + 4);
        Ts[0][j] = v0.x; Ts[1][j] = v0.y; Ts[2][j] = v0.z; Ts[3][j] = v0.w;
        Ts[4][j] = v1.x; Ts[5][j] = v1.y; Ts[6][j] = v1.z; Ts[7][j] = v1.w;
    }
    float zl[NT];
    #pragma unroll
    for (int n = 0; n < NT; n++) zl[n] = g_z[b * KT + h * 8 + n];
    __syncthreads();

    int d = t >> 2, part = t & 3;
    float pn[NT] = {};
    const float* wv = Wv + (size_t)(h * 64 + d) * Hn + part * 256;
    for (int jj = 0; jj < 256; jj += 4) {
        float4 w4 = *(const float4*)(wv + jj);
        int jb = part * 256 + jj;
        #pragma unroll
        for (int n = 0; n < NT; n++) {
            float4 t4 = *(const float4*)&Ts[n][jb];
            pn[n] += w4.x * t4.x + w4.y * t4.y + w4.z * t4.z + w4.w * t4.w;
        }
    }
    #pragma unroll
    for (int n = 0; n < NT; n++) {
        pn[n] += __shfl_xor_sync(0xffffffffu, pn[n], 1);
        pn[n] += __shfl_xor_sync(0xffffffffu, pn[n], 2);
    }
    if (part == 0) {
        float bvd = bv[h * 64 + d];
        #pragma unroll
        for (int n = 0; n < NT; n++) Ms[n][d] = pn[n] + zl[n] * bvd;
    }
    __syncthreads();

    int e = eq * 256 + t;
    float u[NT] = {};
    const float* wo = Wo + (size_t)e * Hn + h * 64;
    #pragma unroll 4
    for (int dd = 0; dd < 64; dd += 4) {
        float4 w4 = *(const float4*)(wo + dd);
        #pragma unroll
        for (int n = 0; n < NT; n++)
            u[n] += w4.x * Ms[n][dd] + w4.y * Ms[n][dd+1]
                  + w4.z * Ms[n][dd+2] + w4.w * Ms[n][dd+3];
    }
    uint32_t w[4];
    #pragma unroll
    for (int q = 0; q < 4; q++)
        w[q] = bf2u(u[q * 2 + 0], u[q * 2 + 1]);
    *(uint4*)(g_Ut + ((size_t)(b * Hn + e)) * KT + h * 8) = make_uint4(w[0], w[1], w[2], w[3]);
}

// ---------------- K6: out = coef@Ut^T + bo + hs via mma.sync (128x128x128) --
#define PADC 136
__global__ void __launch_bounds__(256) k_comb(const float* __restrict__ bo,
                                              const float* __restrict__ hs,
                                              float* __restrict__ out) {
    extern __shared__ __align__(16) __nv_bfloat16 smemc[];
    __nv_bfloat16* sA = smemc;                // coef [128][136]
    __nv_bfloat16* sB = smemc + 128 * PADC;   // Ut   [128][136]
    __shared__ float zs[KT];

    int t = threadIdx.x;
    int bn = blockIdx.x, bm = blockIdx.y;
    int b = bm >> 4;
    int sbase = (bm & 15) * 128;

    if (t < KT) zs[t] = g_z[b * KT + t];

    #pragma unroll
    for (int i = 0; i < 8; i++) {
        int idx = t + 256 * i;
        int row = idx >> 4, c = idx & 15;
        *(uint4*)(sB + row * PADC + c * 8) =
            *(const uint4*)(g_Ut + ((size_t)(b * Hn + bn * 128 + row)) * KT + c * 8);
    }
    __syncthreads();   // zs visible

    {
        int m = t >> 1, hbase = (t & 1) * 8;
        int s = sbase + m;
        #pragma unroll
        for (int hh = 0; hh < 8; hh++) {
            int h = hbase + hh;
            float a = g_qm[(size_t)(b * NHn + h) * Sn + s];
            float c[NT], p = 1.f, den = 0.f;
            #pragma unroll
            for (int n = 0; n < NT; n++) {
                c[n] = p * c_invf[n];
                den += c[n] * zs[h * 8 + n];
                p *= a;
            }
            float inv = (den > 0.f) ? 1.f / den : 0.f;
            uint32_t wv[4];
            #pragma unroll
            for (int q = 0; q < 4; q++)
                wv[q] = bf2u(c[q * 2 + 0] * inv, c[q * 2 + 1] * inv);
            *(uint4*)(sA + m * PADC + h * 8) = make_uint4(wv[0], wv[1], wv[2], wv[3]);
        }
    }
    __syncthreads();

    int wid = t >> 5, lane = t & 31;
    int wm = wid >> 1, wn = wid & 1;
    int R = wm * 32, Cb = wn * 64;
    int g = lane >> 2, tg = lane & 3;

    float acc[2][8][4];
    #pragma unroll
    for (int mi = 0; mi < 2; mi++)
        #pragma unroll
        for (int ni = 0; ni < 8; ni++)
            #pragma unroll
            for (int q = 0; q < 4; q++) acc[mi][ni][q] = 0.f;

    #pragma unroll
    for (int ks = 0; ks < 8; ks++) {
        int k0 = ks * 16;
        uint32_t a[2][4];
        #pragma unroll
        for (int mi = 0; mi < 2; mi++) {
            int r0 = R + mi * 16 + g;
            a[mi][0] = *(const uint32_t*)(sA + r0 * PADC + k0 + 2 * tg);
            a[mi][1] = *(const uint32_t*)(sA + (r0 + 8) * PADC + k0 + 2 * tg);
            a[mi][2] = *(const uint32_t*)(sA + r0 * PADC + k0 + 8 + 2 * tg);
            a[mi][3] = *(const uint32_t*)(sA + (r0 + 8) * PADC + k0 + 8 + 2 * tg);
        }
        #pragma unroll
        for (int ni = 0; ni < 8; ni++) {
            int n = Cb + ni * 8 + g;
            uint32_t bb[2];
            bb[0] = *(const uint32_t*)(sB + n * PADC + k0 + 2 * tg);
            bb[1] = *(const uint32_t*)(sB + n * PADC + k0 + 8 + 2 * tg);
            mma16816(acc[0][ni], a[0], bb);
            mma16816(acc[1][ni], a[1], bb);
        }
    }

    #pragma unroll
    for (int mi = 0; mi < 2; mi++) {
        #pragma unroll
        for (int half = 0; half < 2; half++) {
            int row = bm * 128 + R + mi * 16 + g + half * 8;
            const float* hp = hs + (size_t)row * Hn;
            float* op = out + (size_t)row * Hn;
            #pragma unroll
            for (int ni = 0; ni < 8; ni++) {
                int col = bn * 128 + Cb + ni * 8 + 2 * tg;
                float2 h2 = *(const float2*)(hp + col);
                float2 b2 = *(const float2*)(bo + col);
                float d0 = acc[mi][ni][half * 2 + 0] + h2.x + b2.x;
                float d1 = acc[mi][ni][half * 2 + 1] + h2.y + b2.y;
                *(float2*)(op + col) = make_float2(d0, d1);
            }
        }
    }
}

// ---------------- K7: LayerNorm, warp-per-row (8 rows/block) ----------------
__global__ void __launch_bounds__(256) k_ln(float* __restrict__ x,
                                            const float* __restrict__ w,
                                            const float* __restrict__ bgam) {
    int wrp = threadIdx.x >> 5, l = threadIdx.x & 31;
    int row = blockIdx.x * 8 + wrp;
    float* p = x + (size_t)row * Hn;
    float4 v[8];
    float s = 0.f, q2 = 0.f;
    #pragma unroll
    for (int i = 0; i < 8; i++) {
        v[i] = *(const float4*)(p + (l + 32 * i) * 4);
        s  += v[i].x + v[i].y + v[i].z + v[i].w;
        q2 += v[i].x*v[i].x + v[i].y*v[i].y + v[i].z*v[i].z + v[i].w*v[i].w;
    }
    #pragma unroll
    for (int off = 16; off; off >>= 1) {
        s  += __shfl_xor_sync(0xffffffffu, s, off);
        q2 += __shfl_xor_sync(0xffffffffu, q2, off);
    }
    float mean = s * (1.f / 1024.f);
    float var = q2 * (1.f / 1024.f) - mean * mean;
    float inv = rsqrtf(var + 1e-5f);
    #pragma unroll
    for (int i = 0; i < 8; i++) {
        int c = (l + 32 * i) * 4;
        float4 w4 = *(const float4*)(w + c);
        float4 g4 = *(const float4*)(bgam + c);
        float4 o;
        o.x = (v[i].x - mean) * inv * w4.x + g4.x;
        o.y = (v[i].y - mean) * inv * w4.y + g4.y;
        o.z = (v[i].z - mean) * inv * w4.z + g4.z;
        o.w = (v[i].w - mean) * inv * w4.w + g4.w;
        *(float4*)(p + c) = o;
    }
}

// ---------------- launch: single stream, 7 kernels ----------------
extern "C" void kernel_launch(void* const* d_in, const int* in_sizes, int n_in,
                              void* d_out, int out_size) {
    const float* hs   = (const float*)d_in[0];
    const float* mask = (const float*)d_in[1];
    const float* Wq   = (const float*)d_in[2];
    const float* bq   = (const float*)d_in[3];
    const float* Wk   = (const float*)d_in[4];
    const float* bk   = (const float*)d_in[5];
    const float* Wv   = (const float*)d_in[6];
    const float* bv   = (const float*)d_in[7];
    const float* Wo   = (const float*)d_in[8];
    const float* bo   = (const float*)d_in[9];
    // d_in[10..13]: Wp1,bp1,Wp2,bp2 — dead (one_hot(argmax).sum() == 1)
    const float* lnw  = (const float*)d_in[14];
    const float* lnb  = (const float*)d_in[15];
    float* out = (float*)d_out;

    static int s_attr_done = 0;
    if (!s_attr_done) {
        cudaFuncSetAttribute(k_qkm, cudaFuncAttributeMaxDynamicSharedMemorySize,
                             66048 + 2 * 8704);
        cudaFuncSetAttribute(k_Tg, cudaFuncAttributeMaxDynamicSharedMemorySize,
                             4 * 128 * PAD2 * 2);
        cudaFuncSetAttribute(k_comb, cudaFuncAttributeMaxDynamicSharedMemorySize,
                             2 * 128 * PADC * 2);
        s_attr_done = 1;
    }

    k_bartr<<<128 + 2048, 256>>>(Wq, Wk, bq, bk, hs);
    k_qkm<<<(Bn * Sn) / 32, 256, 66048 + 2 * 8704>>>(hs, mask);
    k_Tg<<<dim3(Hn / 128, KSn, Bn), 256, 4 * 128 * PAD2 * 2>>>();
    k_Tred<<<(Bn * Hn * KT) / 1024, 256>>>();
    k_U<<<dim3(BHn, 4), 256>>>(Wv, bv, Wo);
    k_comb<<<dim3(Hn / 128, (Bn * Sn) / 128), 256, 2 * 128 * PADC * 2>>>(bo, hs, out);
    k_ln<<<(Bn * Sn) / 8, 256>>>(out, lnw, lnb);
}